// round 11
// baseline (speedup 1.0000x reference)
#include <cuda_runtime.h>

#define TLEN   2048
#define CSTEP  16
#define NCHUNK (TLEN / CSTEP)      // 128
#define XSTRIDE 132                // floats per seq chunk block: 16*8 + 4 pad
#define SEQB   32                  // sequences per block

typedef unsigned long long u64;

// Fast HW tanh (MUFU.TANH).
__device__ __forceinline__ float ftanh_fast(float x) {
    float y;
    asm("tanh.approx.f32 %0, %1;" : "=f"(y) : "f"(x));
    return y;
}
// Exact-ish tanh for phase 2.
__device__ __forceinline__ float ftanh_exact(float x) {
    float e = __expf(2.f * x);
    return fmaf(-2.f, __frcp_rn(e + 1.f), 1.f);
}

// ---- packed f32x2 helpers (FFMA2: 2 fp32 MACs per instruction) -------------
__device__ __forceinline__ u64 pk2(float lo, float hi) {
    u64 r; asm("mov.b64 %0, {%1, %2};" : "=l"(r) : "f"(lo), "f"(hi)); return r;
}
__device__ __forceinline__ u64 fma2(u64 a, u64 b, u64 c) {
    u64 d; asm("fma.rn.f32x2 %0, %1, %2, %3;" : "=l"(d) : "l"(a), "l"(b), "l"(c));
    return d;
}
__device__ __forceinline__ float hadd2(u64 v) {
    float lo, hi; asm("mov.b64 {%0, %1}, %2;" : "=f"(lo), "=f"(hi) : "l"(v));
    return lo + hi;
}

// ---------------------------------------------------------------------------
// Single fused kernel (structure identical to the passing R10 kernel; the
// recurrence dot products are restructured as packed f32x2 chains).
// Phase 1: 8 warps; warps 0-3 fwd, 4-7 bwd, same 32 seqs. 3 lane-groups of
//   3 hidden units, 8 seqs/warp. x staged via smem in 16-step chunks with
//   one-chunk-ahead register prefetch. Backward warps walk rows 15->0.
// Phase 2: 25-step H2=32 RNN + 32->3 projection, fused.
// ---------------------------------------------------------------------------
__global__ __launch_bounds__(256) void birnn_kernel(
    const float* __restrict__ x,
    const float* __restrict__ wih_f, const float* __restrict__ whh_f,
    const float* __restrict__ bih_f, const float* __restrict__ bhh_f,
    const float* __restrict__ wih_b, const float* __restrict__ whh_b,
    const float* __restrict__ bih_b, const float* __restrict__ bhh_b,
    const float* __restrict__ wih2, const float* __restrict__ whh2,
    const float* __restrict__ bih2, const float* __restrict__ bhh2,
    const float* __restrict__ wout, const float* __restrict__ bout,
    float* __restrict__ out)
{
    __shared__ __align__(16) float xs[2 * SEQB * XSTRIDE];   // 33,792 B
    __shared__ float ys[SEQB * 19];                          // phase1 -> phase2

    const int tid  = threadIdx.x;
    const int warp = tid >> 5;          // 0..7
    const int lane = tid & 31;
    const int isB  = warp >> 2;         // 0 fwd, 1 bwd
    const int wq   = warp & 3;
    const int g    = lane >> 3;         // unit-group 0..2 (3 = idle)
    const int r    = lane & 7;          // seq slot within warp
    const int s_loc = wq * 8 + r;       // block-local seq 0..31
    const bool act = (g < 3);

    const float* Wih = isB ? wih_b : wih_f;
    const float* Whh = isB ? whh_b : whh_f;
    const float* Bi  = isB ? bih_b : bih_f;
    const float* Bh  = isB ? bhh_b : bhh_f;

    // ring-exchange source lanes
    const int gp1 = (g + 1) % 3, gp2 = (g + 2) % 3;
    const int src1 = gp1 * 8 + r;
    const int src2 = gp2 * 8 + r;

    // ---- load weights, permute whh columns to arrival order, pack as f32x2
    // operand pair layout per step:
    //   p0=(x0,x1) p1=(x2,x3) p2=(x4,hv0) p3=(hv1,hv2)
    //   p4=(hv3,hv4) p5=(hv5,hv6) p6=(hv7,hv8)
    u64 Wp[3][7];
    u64 bp[3];
    {
        float wih[3][5], whh[3][9];
#pragma unroll
        for (int k = 0; k < 3; k++) {
            const int u = 3 * g + k;
#pragma unroll
            for (int j = 0; j < 5; j++)
                wih[k][j] = act ? Wih[u * 5 + j] : 0.f;
#pragma unroll
            for (int m = 0; m < 3; m++) {
                const int grp = (g + m) % 3;
#pragma unroll
                for (int j2 = 0; j2 < 3; j2++)
                    whh[k][3 * m + j2] = act ? Whh[u * 9 + 3 * grp + j2] : 0.f;
            }
            const float bias = act ? (Bi[u] + Bh[u]) : 0.f;
            Wp[k][0] = pk2(wih[k][0], wih[k][1]);
            Wp[k][1] = pk2(wih[k][2], wih[k][3]);
            Wp[k][2] = pk2(wih[k][4], whh[k][0]);
            Wp[k][3] = pk2(whh[k][1], whh[k][2]);
            Wp[k][4] = pk2(whh[k][3], whh[k][4]);
            Wp[k][5] = pk2(whh[k][5], whh[k][6]);
            Wp[k][6] = pk2(whh[k][7], whh[k][8]);
            bp[k] = pk2(bias, 0.f);
        }
    }

    float hv0 = 0.f, hv1 = 0.f, hv2 = 0.f;     // own units (prev step)
    float hv3 = 0.f, hv4 = 0.f, hv5 = 0.f;     // group g+1
    float hv6 = 0.f, hv7 = 0.f, hv8 = 0.f;     // group g+2

    // -------- staged x prefetch: 1280 float4 per chunk-pair, 5 per thread ----
    float4 st[5];
    auto loadStage = [&](int cn) {
        const int valid = (cn < NCHUNK);
        const int t4f = valid ? 20 * cn : 0;
        const int t4b = valid ? (2540 - 20 * cn) : 2540;
#pragma unroll
        for (int it = 0; it < 5; it++) {
            const int idx = tid + it * 256;             // 0..1279
            const int buf = (idx >= 640);
            const int rem = idx - buf * 640;
            const int s   = rem / 20;
            const int k   = rem - s * 20;
            const int bg  = blockIdx.x * SEQB + s;
            const int f4i = bg * 2560 + (buf ? t4b : t4f) + k;
            st[it] = __ldg((const float4*)x + f4i);
        }
    };
    auto storeStage = [&]() {
#pragma unroll
        for (int it = 0; it < 5; it++) {
            const int idx = tid + it * 256;
            const int buf = (idx >= 640);
            const int rem = idx - buf * 640;
            const int s   = rem / 20;
            const int k   = rem - s * 20;
            float v[4] = { st[it].x, st[it].y, st[it].z, st[it].w };
#pragma unroll
            for (int jj = 0; jj < 4; jj++) {
                const int f = 4 * k + jj;               // 0..79
                const int trow = f / 5;                 // local time 0..15
                const int j = f - 5 * trow;
                xs[buf * (SEQB * XSTRIDE) + s * XSTRIDE + trow * 8 + j] = v[jj];
            }
        }
    };

    // backward warps walk rows 15 -> 0 (the ONLY time reversal)
    const float* xp0 = xs + isB * (SEQB * XSTRIDE) + s_loc * XSTRIDE + (isB ? 120 : 0);
    const int dstep = isB ? -8 : 8;

    loadStage(0);
    for (int c = 0; c < NCHUNK; c++) {
        storeStage();
        __syncthreads();
        loadStage(c + 1);           // hidden under the 16-step compute below

        const float* p = xp0;
#pragma unroll
        for (int i = 0; i < CSTEP; i++) {
            const float4 xv = *(const float4*)p;
            const float  x4 = p[4];
            p += dstep;

            // chain head: x terms (ready early); tail: shfl-dependent pairs
            const u64 p0 = pk2(xv.x, xv.y);
            const u64 p1 = pk2(xv.z, xv.w);
            const u64 p2 = pk2(x4,  hv0);
            const u64 p3 = pk2(hv1, hv2);
            const u64 p4 = pk2(hv3, hv4);
            const u64 p5 = pk2(hv5, hv6);
            const u64 p6 = pk2(hv7, hv8);

            u64 ac0 = fma2(p0, Wp[0][0], bp[0]);
            u64 ac1 = fma2(p0, Wp[1][0], bp[1]);
            u64 ac2 = fma2(p0, Wp[2][0], bp[2]);
            ac0 = fma2(p1, Wp[0][1], ac0);
            ac1 = fma2(p1, Wp[1][1], ac1);
            ac2 = fma2(p1, Wp[2][1], ac2);
            ac0 = fma2(p2, Wp[0][2], ac0);
            ac1 = fma2(p2, Wp[1][2], ac1);
            ac2 = fma2(p2, Wp[2][2], ac2);
            ac0 = fma2(p3, Wp[0][3], ac0);
            ac1 = fma2(p3, Wp[1][3], ac1);
            ac2 = fma2(p3, Wp[2][3], ac2);
            ac0 = fma2(p4, Wp[0][4], ac0);
            ac1 = fma2(p4, Wp[1][4], ac1);
            ac2 = fma2(p4, Wp[2][4], ac2);
            ac0 = fma2(p5, Wp[0][5], ac0);
            ac1 = fma2(p5, Wp[1][5], ac1);
            ac2 = fma2(p5, Wp[2][5], ac2);
            ac0 = fma2(p6, Wp[0][6], ac0);
            ac1 = fma2(p6, Wp[1][6], ac1);
            ac2 = fma2(p6, Wp[2][6], ac2);

            const float n0 = ftanh_fast(hadd2(ac0));
            const float n1 = ftanh_fast(hadd2(ac1));
            const float n2 = ftanh_fast(hadd2(ac2));

            hv0 = n0; hv1 = n1; hv2 = n2;
            hv3 = __shfl_sync(0xffffffffu, n0, src1);
            hv4 = __shfl_sync(0xffffffffu, n1, src1);
            hv5 = __shfl_sync(0xffffffffu, n2, src1);
            hv6 = __shfl_sync(0xffffffffu, n0, src2);
            hv7 = __shfl_sync(0xffffffffu, n1, src2);
            hv8 = __shfl_sync(0xffffffffu, n2, src2);
        }
        __syncthreads();
    }

    // final hidden -> ys[s][dir*9 + u]
    if (act) {
        ys[s_loc * 19 + isB * 9 + 3 * g + 0] = hv0;
        ys[s_loc * 19 + isB * 9 + 3 * g + 1] = hv1;
        ys[s_loc * 19 + isB * 9 + 3 * g + 2] = hv2;
    }
    __syncthreads();

    // ---------------- Phase 2: each warp handles 4 batch elements ----------
    float wh[32];
    {
        const float4* pw = (const float4*)(whh2 + lane * 32);
#pragma unroll
        for (int q = 0; q < 8; q++) {
            float4 v = pw[q];
            wh[q * 4 + 0] = v.x; wh[q * 4 + 1] = v.y;
            wh[q * 4 + 2] = v.z; wh[q * 4 + 3] = v.w;
        }
    }
    float wi[18];
#pragma unroll
    for (int j = 0; j < 18; j++) wi[j] = wih2[lane * 18 + j];
    const float bias2 = bih2[lane] + bhh2[lane];
    const float bo0 = bout[0], bo1 = bout[1], bo2 = bout[2];

    float* hsbuf = xs + warp * 825;     // reuse xs: 8 warps x 25*33 floats

    for (int q = 0; q < 4; q++) {
        const int bl = warp * 4 + q;
        const long bg = (long)blockIdx.x * SEQB + bl;

        const float yv = (lane < 18) ? ys[bl * 19 + lane] : 0.f;
        float pre = bias2;
#pragma unroll
        for (int j = 0; j < 18; j++)
            pre = fmaf(__shfl_sync(0xffffffffu, yv, j), wi[j], pre);
        float h = ftanh_exact(pre);
        hsbuf[0 * 33 + lane] = h;

#pragma unroll 4
        for (int t = 1; t < 25; t++) {
            float pacc = bias2;
#pragma unroll
            for (int j = 0; j < 32; j++)
                pacc = fmaf(__shfl_sync(0xffffffffu, h, j), wh[j], pacc);
            h = ftanh_exact(pacc);
            hsbuf[t * 33 + lane] = h;
        }
        __syncwarp();

        if (lane < 25) {
            float a0 = bo0, a1 = bo1, a2 = bo2;
            const float* hrow = hsbuf + lane * 33;
#pragma unroll
            for (int j = 0; j < 32; j++) {
                const float hvv = hrow[j];
                a0 = fmaf(hvv, wout[j],      a0);
                a1 = fmaf(hvv, wout[32 + j], a1);
                a2 = fmaf(hvv, wout[64 + j], a2);
            }
            float* ob = out + bg * 75 + lane * 3;
            ob[0] = a0; ob[1] = a1; ob[2] = a2;
        }
        __syncwarp();
    }
}

extern "C" void kernel_launch(void* const* d_in, const int* in_sizes, int n_in,
                              void* d_out, int out_size)
{
    const float* x      = (const float*)d_in[0];
    const float* wih_f  = (const float*)d_in[1];
    const float* whh_f  = (const float*)d_in[2];
    const float* bih_f  = (const float*)d_in[3];
    const float* bhh_f  = (const float*)d_in[4];
    const float* wih_b  = (const float*)d_in[5];
    const float* whh_b  = (const float*)d_in[6];
    const float* bih_b  = (const float*)d_in[7];
    const float* bhh_b  = (const float*)d_in[8];
    const float* wih2   = (const float*)d_in[9];
    const float* whh2   = (const float*)d_in[10];
    const float* bih2   = (const float*)d_in[11];
    const float* bhh2   = (const float*)d_in[12];
    const float* wout   = (const float*)d_in[13];
    const float* bout   = (const float*)d_in[14];
    float* out = (float*)d_out;

    const int B = in_sizes[0] / (TLEN * 5);      // 4096
    birnn_kernel<<<B / SEQB, 256>>>(x,
        wih_f, whh_f, bih_f, bhh_f,
        wih_b, whh_b, bih_b, bhh_b,
        wih2, whh2, bih2, bhh2, wout, bout, out);
}